// round 6
// baseline (speedup 1.0000x reference)
#include <cuda_runtime.h>

// ---------------------------------------------------------------------------
// TexturedSoftPhongShader — R5: single fused kernel, inline faces->vn gather
// on the (rare) active path; no prep kernel, no scratch buffer.
// Inputs (metadata order):
//  0 texels (N,H,W,K,3) f32 | 1 bary (N,H,W,K,3) f32 | 2 zbuf (N,H,W,K) f32
//  3 dists (N,H,W,K) f32 | 4 verts (unused) | 5 vertex_normals (V,3) f32
//  6 gamma (N,27) f32 | 7 pix_to_face (N,H,W,K) i32 | 8 faces (F,3) i32
// Output: (N,H,W,4) f32
// ---------------------------------------------------------------------------

__global__ __launch_bounds__(256, 4)
void shade_kernel(const float*  __restrict__ texels,
                  const float*  __restrict__ bary,
                  const float4* __restrict__ zbuf4,
                  const float4* __restrict__ dists4,
                  const int4*   __restrict__ p2f4,
                  const float*  __restrict__ gamma,
                  const float*  __restrict__ vn,
                  const int*    __restrict__ faces,
                  float4*       __restrict__ out,
                  int HW, int P) {
    const float A0C0   = 0.8862269254527580f;
    const float A1C1   = 1.7724538509055159f;
    const float A2C2   = 2.4270323670f;
    const float A2C2D0 = 0.7006239630f;

    const float EPS       = 1e-10f;
    const float INV_SIGMA = 1e4f;
    const float INV_GAMMA = 1e4f;
    const float INV_ZR    = 1.0f / 99.0f;

    // Folded per-image SH coefficients: lighting is evaluated on RAW vertex
    // normals; the (-1,-1,1) flip, +0.8 bias, and (3z^2-1) constant are all
    // folded into these 27 numbers.
    __shared__ float sC[9][3];
    int tid  = threadIdx.x;
    int pix0 = blockIdx.x * 256;
    if (tid < 3) {
        int c = tid;
        int n0 = pix0 / HW;
        const float* gp = gamma + n0 * 27 + c * 9;
        float g0 = gp[0] + 0.8f;
        float g6 = gp[6];
        sC[0][c] = A0C0 * g0 - A2C2D0 * g6;
        sC[1][c] = A1C1 * gp[1];
        sC[2][c] = A1C1 * gp[2];
        sC[3][c] = A1C1 * gp[3];
        sC[4][c] = A2C2 * gp[4];
        sC[5][c] = A2C2 * gp[5];
        sC[6][c] = 3.0f * A2C2D0 * g6;
        sC[7][c] = A2C2 * gp[7];
        sC[8][c] = A2C2 * 0.5f * gp[8];
    }
    __syncthreads();

    int pix = pix0 + tid;
    if (pix >= P) return;

    float4 z4 = zbuf4[pix];
    float4 d4 = dists4[pix];
    int4   f4 = p2f4[pix];
    float zv[4] = {z4.x, z4.y, z4.z, z4.w};
    float dv[4] = {d4.x, d4.y, d4.z, d4.w};
    int   fv[4] = {f4.x, f4.y, f4.z, f4.w};

    // Pass 1: z_inv + max
    float zi[4];
    float zmax = EPS;
#pragma unroll
    for (int k = 0; k < 4; k++) {
        bool m = fv[k] >= 0;
        zi[k] = m ? (100.0f - zv[k]) * INV_ZR : 0.0f;
        zmax = fmaxf(zmax, zi[k]);
    }

    const float* tp = texels + (size_t)pix * 12;
    const float* bp = bary   + (size_t)pix * 12;

    // Pass 2: alpha product for all valid samples; full gather+lighting ONLY
    // where the blend weight is representable in f32 (exp underflows to an
    // exact 0 in the reference too; skipped term bounded by ~1e-28).
    float accR = 0.f, accG = 0.f, accB = 0.f;
    float wsum = 0.f;
    float oma  = 1.f;
#pragma unroll
    for (int k = 0; k < 4; k++) {
        if (fv[k] >= 0) {
            float prob = __fdividef(1.0f, 1.0f + __expf(dv[k] * INV_SIGMA));
            oma *= (1.0f - prob);
            float arg = (zi[k] - zmax) * INV_GAMMA;
            if (arg > -87.0f) {
                float w = prob * __expf(arg);
                wsum += w;

                // Inline double-gather: faces row (12B, ~1 sector) then the
                // three vertex-normal rows. faces+vn are L2-resident.
                const int* fr = faces + 3 * fv[k];
                int i0 = fr[0], i1 = fr[1], i2 = fr[2];
                const float* n0 = vn + 3 * i0;
                const float* n1 = vn + 3 * i1;
                const float* n2 = vn + 3 * i2;
                float b0 = bp[3 * k + 0], b1 = bp[3 * k + 1], b2 = bp[3 * k + 2];
                float mx = b0 * n0[0] + b1 * n1[0] + b2 * n2[0];
                float my = b0 * n0[1] + b1 * n1[1] + b2 * n2[1];
                float mz = b0 * n0[2] + b1 * n1[2] + b2 * n2[2];

                float pxy = mx * my;
                float pyz = my * mz;
                float pxz = mx * mz;
                float pzz = mz * mz;
                float pd  = fmaf(-my, my, mx * mx);

                float Lr = sC[0][0] + sC[1][0]*my + sC[2][0]*mz + sC[3][0]*mx
                         + sC[4][0]*pxy + sC[5][0]*pyz + sC[6][0]*pzz
                         + sC[7][0]*pxz + sC[8][0]*pd;
                float Lg = sC[0][1] + sC[1][1]*my + sC[2][1]*mz + sC[3][1]*mx
                         + sC[4][1]*pxy + sC[5][1]*pyz + sC[6][1]*pzz
                         + sC[7][1]*pxz + sC[8][1]*pd;
                float Lb = sC[0][2] + sC[1][2]*my + sC[2][2]*mz + sC[3][2]*mx
                         + sC[4][2]*pxy + sC[5][2]*pyz + sC[6][2]*pzz
                         + sC[7][2]*pxz + sC[8][2]*pd;

                accR = fmaf(w, Lr * tp[3 * k + 0], accR);
                accG = fmaf(w, Lg * tp[3 * k + 1], accG);
                accB = fmaf(w, Lb * tp[3 * k + 2], accB);
            }
        }
    }

    float delta  = fmaxf(__expf((EPS - zmax) * INV_GAMMA), EPS);
    float invden = __fdividef(1.0f, wsum + delta);
    float bg     = delta * invden;

    float4 o;
    o.x = fmaf(accR, invden, bg);
    o.y = fmaf(accG, invden, bg);
    o.z = fmaf(accB, invden, bg);
    o.w = 1.0f - oma;
    out[pix] = o;
}

extern "C" void kernel_launch(void* const* d_in, const int* in_sizes, int n_in,
                              void* d_out, int out_size) {
    const float* texels = (const float*)d_in[0];
    const float* bary   = (const float*)d_in[1];
    const float* zbuf   = (const float*)d_in[2];
    const float* dists  = (const float*)d_in[3];
    const float* vn     = (const float*)d_in[5];
    const float* gamma  = (const float*)d_in[6];
    const int*   p2f    = (const int*)d_in[7];
    const int*   faces  = (const int*)d_in[8];

    int P = in_sizes[2] / 4;
    int N = in_sizes[6] / 27;
    int HW = P / N;

    shade_kernel<<<(P + 255) / 256, 256>>>(
        texels, bary,
        (const float4*)zbuf, (const float4*)dists,
        (const int4*)p2f, gamma, vn, faces, (float4*)d_out, HW, P);
}

// round 9
// speedup vs baseline: 1.4968x; 1.4968x over previous
#include <cuda_runtime.h>

// ---------------------------------------------------------------------------
// TexturedSoftPhongShader — R6: R4 shade (best) + corner-parallel fast prep
// Inputs (metadata order):
//  0 texels (N,H,W,K,3) f32 | 1 bary (N,H,W,K,3) f32 | 2 zbuf (N,H,W,K) f32
//  3 dists (N,H,W,K) f32 | 4 verts (unused) | 5 vertex_normals (V,3) f32
//  6 gamma (N,27) f32 | 7 pix_to_face (N,H,W,K) i32 | 8 faces (F,3) i32
// Output: (N,H,W,4) f32
// ---------------------------------------------------------------------------

#define MAXF 70000

// 64B per face record (3 corners + pad): record never straddles a 128B line.
__device__ float4 g_fn[MAXF * 4];

// Corner-parallel: one thread per (face, corner). faces[] reads coalesced,
// vn rows L2-resident, one STG.128 out. 3x parallelism of face-parallel prep.
__global__ __launch_bounds__(256)
void prep_kernel(const int* __restrict__ faces,
                 const float* __restrict__ vn, int FC) {
    int idx = blockIdx.x * blockDim.x + threadIdx.x;   // 0 .. 3F-1
    if (idx >= FC) return;
    int f      = idx / 3;
    int corner = idx - 3 * f;
    int v      = faces[idx];
    const float* nr = vn + 3 * v;
    g_fn[4 * f + corner] = make_float4(nr[0], nr[1], nr[2], 0.f);
}

__global__ __launch_bounds__(256, 4)
void shade_kernel(const float*  __restrict__ texels,
                  const float*  __restrict__ bary,
                  const float4* __restrict__ zbuf4,
                  const float4* __restrict__ dists4,
                  const int4*   __restrict__ p2f4,
                  const float*  __restrict__ gamma,
                  float4*       __restrict__ out,
                  int HW, int P) {
    const float A0C0   = 0.8862269254527580f;
    const float A1C1   = 1.7724538509055159f;
    const float A2C2   = 2.4270323670f;
    const float A2C2D0 = 0.7006239630f;

    const float EPS       = 1e-10f;
    const float INV_SIGMA = 1e4f;
    const float INV_GAMMA = 1e4f;
    const float INV_ZR    = 1.0f / 99.0f;

    // Folded per-image SH coefficients (flip, +0.8 bias, (3z^2-1) const folded)
    __shared__ float sC[9][3];
    int tid  = threadIdx.x;
    int pix0 = blockIdx.x * 256;
    if (tid < 3) {
        int c = tid;
        int n0 = pix0 / HW;
        const float* gp = gamma + n0 * 27 + c * 9;
        float g0 = gp[0] + 0.8f;
        float g6 = gp[6];
        sC[0][c] = A0C0 * g0 - A2C2D0 * g6;
        sC[1][c] = A1C1 * gp[1];
        sC[2][c] = A1C1 * gp[2];
        sC[3][c] = A1C1 * gp[3];
        sC[4][c] = A2C2 * gp[4];
        sC[5][c] = A2C2 * gp[5];
        sC[6][c] = 3.0f * A2C2D0 * g6;
        sC[7][c] = A2C2 * gp[7];
        sC[8][c] = A2C2 * 0.5f * gp[8];
    }
    __syncthreads();

    int pix = pix0 + tid;
    if (pix >= P) return;

    float4 z4 = zbuf4[pix];
    float4 d4 = dists4[pix];
    int4   f4 = p2f4[pix];
    float zv[4] = {z4.x, z4.y, z4.z, z4.w};
    float dv[4] = {d4.x, d4.y, d4.z, d4.w};
    int   fv[4] = {f4.x, f4.y, f4.z, f4.w};

    // Pass 1: z_inv + max
    float zi[4];
    float zmax = EPS;
#pragma unroll
    for (int k = 0; k < 4; k++) {
        bool m = fv[k] >= 0;
        zi[k] = m ? (100.0f - zv[k]) * INV_ZR : 0.0f;
        zmax = fmaxf(zmax, zi[k]);
    }

    const float* tp = texels + (size_t)pix * 12;
    const float* bp = bary   + (size_t)pix * 12;

    // Pass 2: alpha product for all valid samples; gather+lighting ONLY where
    // the blend weight is representable (exp underflow => exact 0 in the
    // reference too; skipped term bounded by ~1e-28).
    float accR = 0.f, accG = 0.f, accB = 0.f;
    float wsum = 0.f;
    float oma  = 1.f;
#pragma unroll
    for (int k = 0; k < 4; k++) {
        if (fv[k] >= 0) {
            float prob = __fdividef(1.0f, 1.0f + __expf(dv[k] * INV_SIGMA));
            oma *= (1.0f - prob);
            float arg = (zi[k] - zmax) * INV_GAMMA;
            if (arg > -87.0f) {
                float w = prob * __expf(arg);
                wsum += w;

                float b0 = bp[3 * k + 0], b1 = bp[3 * k + 1], b2 = bp[3 * k + 2];
                const float4* fp = g_fn + 4 * fv[k];
                float4 v0 = fp[0];
                float4 v1 = fp[1];
                float4 v2 = fp[2];
                float mx = b0 * v0.x + b1 * v1.x + b2 * v2.x;
                float my = b0 * v0.y + b1 * v1.y + b2 * v2.y;
                float mz = b0 * v0.z + b1 * v1.z + b2 * v2.z;

                float pxy = mx * my;
                float pyz = my * mz;
                float pxz = mx * mz;
                float pzz = mz * mz;
                float pd  = fmaf(-my, my, mx * mx);

                float Lr = sC[0][0] + sC[1][0]*my + sC[2][0]*mz + sC[3][0]*mx
                         + sC[4][0]*pxy + sC[5][0]*pyz + sC[6][0]*pzz
                         + sC[7][0]*pxz + sC[8][0]*pd;
                float Lg = sC[0][1] + sC[1][1]*my + sC[2][1]*mz + sC[3][1]*mx
                         + sC[4][1]*pxy + sC[5][1]*pyz + sC[6][1]*pzz
                         + sC[7][1]*pxz + sC[8][1]*pd;
                float Lb = sC[0][2] + sC[1][2]*my + sC[2][2]*mz + sC[3][2]*mx
                         + sC[4][2]*pxy + sC[5][2]*pyz + sC[6][2]*pzz
                         + sC[7][2]*pxz + sC[8][2]*pd;

                accR = fmaf(w, Lr * tp[3 * k + 0], accR);
                accG = fmaf(w, Lg * tp[3 * k + 1], accG);
                accB = fmaf(w, Lb * tp[3 * k + 2], accB);
            }
        }
    }

    float delta  = fmaxf(__expf((EPS - zmax) * INV_GAMMA), EPS);
    float invden = __fdividef(1.0f, wsum + delta);
    float bg     = delta * invden;

    float4 o;
    o.x = fmaf(accR, invden, bg);
    o.y = fmaf(accG, invden, bg);
    o.z = fmaf(accB, invden, bg);
    o.w = 1.0f - oma;
    out[pix] = o;
}

extern "C" void kernel_launch(void* const* d_in, const int* in_sizes, int n_in,
                              void* d_out, int out_size) {
    const float* texels = (const float*)d_in[0];
    const float* bary   = (const float*)d_in[1];
    const float* zbuf   = (const float*)d_in[2];
    const float* dists  = (const float*)d_in[3];
    const float* vn     = (const float*)d_in[5];
    const float* gamma  = (const float*)d_in[6];
    const int*   p2f    = (const int*)d_in[7];
    const int*   faces  = (const int*)d_in[8];

    int FC = in_sizes[8];            // 3*F corner count
    if (FC > MAXF * 3) FC = MAXF * 3;
    int P = in_sizes[2] / 4;
    int N = in_sizes[6] / 27;
    int HW = P / N;

    prep_kernel<<<(FC + 255) / 256, 256>>>(faces, vn, FC);
    shade_kernel<<<(P + 255) / 256, 256>>>(
        texels, bary,
        (const float4*)zbuf, (const float4*)dists,
        (const int4*)p2f, gamma, (float4*)d_out, HW, P);
}